// round 1
// baseline (speedup 1.0000x reference)
#include <cuda_runtime.h>

#define NQ     14
#define DIM    16384          // 2^14
#define BATCH  128
#define NGATES 26
#define NOBS   11
#define ENC    390
#define INDIM  784
#define CTHREADS 512

// ---------------- device scratch (no allocation allowed) ----------------
__device__ float  g_enc[BATCH * ENC];
__device__ float2 g_U[NGATES * BATCH * 16];
__device__ float2 g_H[NOBS * 256];

// ---------------- complex helpers ----------------
__device__ __forceinline__ float2 cfma(float2 a, float2 b, float2 c) {
    c.x = fmaf(a.x, b.x, c.x); c.x = fmaf(-a.y, b.y, c.x);
    c.y = fmaf(a.x, b.y, c.y); c.y = fmaf( a.y, b.x, c.y);
    return c;
}

// ---------------- Pauli table for SU(4) generator ----------------
// 15 words: IX,IY,IZ,XI,XX,XY,XZ,YI,YX,YY,YZ,ZI,ZX,ZY,ZZ; each has 4 nonzeros {r,c,re,im}
__constant__ signed char PT[60][4] = {
 {0,1,1,0},{1,0,1,0},{2,3,1,0},{3,2,1,0},          // IX
 {0,1,0,-1},{1,0,0,1},{2,3,0,-1},{3,2,0,1},        // IY
 {0,0,1,0},{1,1,-1,0},{2,2,1,0},{3,3,-1,0},        // IZ
 {0,2,1,0},{1,3,1,0},{2,0,1,0},{3,1,1,0},          // XI
 {0,3,1,0},{1,2,1,0},{2,1,1,0},{3,0,1,0},          // XX
 {0,3,0,-1},{1,2,0,1},{2,1,0,-1},{3,0,0,1},        // XY
 {0,2,1,0},{1,3,-1,0},{2,0,1,0},{3,1,-1,0},        // XZ
 {0,2,0,-1},{1,3,0,-1},{2,0,0,1},{3,1,0,1},        // YI
 {0,3,0,-1},{1,2,0,-1},{2,1,0,1},{3,0,0,1},        // YX
 {0,3,-1,0},{1,2,1,0},{2,1,1,0},{3,0,-1,0},        // YY
 {0,2,0,-1},{1,3,0,1},{2,0,0,1},{3,1,0,-1},        // YZ
 {0,0,1,0},{1,1,1,0},{2,2,-1,0},{3,3,-1,0},        // ZI
 {0,1,1,0},{1,0,1,0},{2,3,-1,0},{3,2,-1,0},        // ZX
 {0,1,0,-1},{1,0,0,1},{2,3,0,1},{3,2,0,-1},        // ZY
 {0,0,1,0},{1,1,-1,0},{2,2,-1,0},{3,3,1,0},        // ZZ
};

// ---------------- kernel 1: encoded = x @ W^T + b ----------------
__global__ void encode_kernel(const float* __restrict__ x,
                              const float* __restrict__ W,
                              const float* __restrict__ bv) {
    __shared__ float wrow[INDIM];
    int j = blockIdx.x;                       // 390 blocks
    for (int k = threadIdx.x; k < INDIM; k += blockDim.x) wrow[k] = W[j * INDIM + k];
    __syncthreads();
    int b = threadIdx.x;                      // 128 threads
    const float* xr = x + b * INDIM;
    float acc = 0.f;
    #pragma unroll 8
    for (int k = 0; k < INDIM; k++) acc = fmaf(xr[k], wrow[k], acc);
    g_enc[b * ENC + j] = acc + bv[j];
}

// ---------------- kernel 2: build 11 Hermitian observables ----------------
__global__ void herm_kernel(const float* __restrict__ A,
                            const float* __restrict__ Bp,
                            const float* __restrict__ D) {
    int w = blockIdx.x;                       // 11 blocks x 256 threads
    int idx = threadIdx.x;
    int r = idx >> 4, c = idx & 15;
    float2 h;
    if (r > c)       { int p = r * (r - 1) / 2 + c; h = make_float2(A[w*120+p],  Bp[w*120+p]); }
    else if (r < c)  { int p = c * (c - 1) / 2 + r; h = make_float2(A[w*120+p], -Bp[w*120+p]); }
    else             { float dv = (r < 15) ? D[w*16 + r + 1] : 0.f; h = make_float2(2.f*dv, 0.f); }
    g_H[w * 256 + idx] = h;
}

// ---------------- kernel 3: U = expm(i * sum theta_m P_m) per (gate,batch) ----------------
__device__ __forceinline__ void cmm4(const float2* A, const float2* B, float2* C) {
    #pragma unroll
    for (int r = 0; r < 4; r++)
        #pragma unroll
        for (int c = 0; c < 4; c++) {
            float2 acc = make_float2(0.f, 0.f);
            #pragma unroll
            for (int k = 0; k < 4; k++) acc = cfma(A[r*4+k], B[k*4+c], acc);
            C[r*4+c] = acc;
        }
}

__global__ void su4_kernel() {
    int id = blockIdx.x * blockDim.x + threadIdx.x;
    if (id >= NGATES * BATCH) return;
    int g = id >> 7, b = id & 127;
    const float* th = g_enc + b * ENC + g * 15;

    float2 H[16];
    #pragma unroll
    for (int e = 0; e < 16; e++) H[e] = make_float2(0.f, 0.f);
    #pragma unroll
    for (int m = 0; m < 15; m++) {
        float t = th[m];
        #pragma unroll
        for (int e = 0; e < 4; e++) {
            int r = PT[m*4+e][0], c = PT[m*4+e][1];
            H[r*4+c].x = fmaf(t, (float)PT[m*4+e][2], H[r*4+c].x);
            H[r*4+c].y = fmaf(t, (float)PT[m*4+e][3], H[r*4+c].y);
        }
    }
    float fro2 = 0.f;
    #pragma unroll
    for (int e = 0; e < 16; e++) fro2 += H[e].x*H[e].x + H[e].y*H[e].y;
    float fro = sqrtf(fro2);
    int s = 0; float sc = 1.f;
    while (fro * sc > 0.4f && s < 30) { sc *= 0.5f; s++; }

    float2 Am[16];
    #pragma unroll
    for (int e = 0; e < 16; e++) Am[e] = make_float2(-H[e].y * sc, H[e].x * sc);  // i*H*sc

    float2 R[16], Tm[16];
    #pragma unroll
    for (int e = 0; e < 16; e++) R[e] = make_float2((e % 5 == 0) ? 1.f : 0.f, 0.f);
    for (int j = 12; j >= 1; j--) {          // Horner Taylor
        cmm4(Am, R, Tm);
        float inv = 1.f / (float)j;
        #pragma unroll
        for (int e = 0; e < 16; e++)
            R[e] = make_float2(fmaf(Tm[e].x, inv, (e % 5 == 0) ? 1.f : 0.f), Tm[e].y * inv);
    }
    for (int t2 = 0; t2 < s; t2++) {         // squaring
        cmm4(R, R, Tm);
        #pragma unroll
        for (int e = 0; e < 16; e++) R[e] = Tm[e];
    }
    #pragma unroll
    for (int e = 0; e < 16; e++) g_U[id * 16 + e] = R[e];
}

// ---------------- kernel 4: full circuit, state resident in SMEM ----------------
__device__ __forceinline__ void ry16(float2* v, int m, float c, float s) {
    #pragma unroll
    for (int k = 0; k < 16; k++) if (!(k & m)) {
        float2 a = v[k], bb = v[k | m];
        v[k].x     = fmaf(c, a.x, -s * bb.x);
        v[k].y     = fmaf(c, a.y, -s * bb.y);
        v[k | m].x = fmaf(s, a.x,  c * bb.x);
        v[k | m].y = fmaf(s, a.y,  c * bb.y);
    }
}
__device__ __forceinline__ void cnot16(float2* v, int cm, int tm) {
    #pragma unroll
    for (int k = 0; k < 16; k++)
        if ((k & cm) && !(k & tm)) { float2 t = v[k]; v[k] = v[k | tm]; v[k | tm] = t; }
}

__global__ void __launch_bounds__(CTHREADS, 1)
circuit_kernel(const float* __restrict__ var,
               const float* __restrict__ Wh,
               const float* __restrict__ bh,
               float* __restrict__ out) {
    extern __shared__ float smraw[];
    float2* st   = (float2*)smraw;          // 16384
    float2* Us   = st + DIM;                // 26*16 = 416
    float2* Hsm  = Us + 416;                // 11*256 = 2816
    float*  ry   = (float*)(Hsm + 2816);    // 84
    float*  red  = ry + 84;                 // 16
    float*  qout = red + 16;                // 11

    const int b = blockIdx.x, tid = threadIdx.x;

    for (int i = tid; i < 416; i += CTHREADS) {
        int g = i >> 4, e = i & 15;
        Us[i] = g_U[((g << 7) | b) * 16 + e];
    }
    for (int i = tid; i < NOBS * 256; i += CTHREADS) Hsm[i] = g_H[i];
    for (int i = tid; i < 42; i += CTHREADS) {
        float t = var[i] * 0.5f;
        ry[2*i] = cosf(t); ry[2*i+1] = sinf(t);
    }
    for (int i = tid; i < DIM; i += CTHREADS)
        st[i] = (i == 0) ? make_float2(1.f, 0.f) : make_float2(0.f, 0.f);
    __syncthreads();

    // ---- 26 SU(4) gates ----
    const int qtab[NGATES] = {0,2,4,6,8,10,12,1,3,5,7,9,11, 0,2,4,6,8,10,12,1,3,5,7,9,11};
    for (int g = 0; g < NGATES; g++) {
        int q = qtab[g], pos = 12 - q, s4 = 1 << pos;
        float2 u[16];
        #pragma unroll
        for (int e = 0; e < 16; e++) u[e] = Us[g * 16 + e];
        for (int grp = tid; grp < 4096; grp += CTHREADS) {
            int low = grp & (s4 - 1);
            int base = ((grp >> pos) << (pos + 2)) | low;
            float2 a0 = st[base], a1 = st[base + s4], a2 = st[base + 2*s4], a3 = st[base + 3*s4];
            float2 o0 = make_float2(0,0), o1 = make_float2(0,0), o2 = make_float2(0,0), o3 = make_float2(0,0);
            o0 = cfma(u[0],  a0, o0); o0 = cfma(u[1],  a1, o0); o0 = cfma(u[2],  a2, o0); o0 = cfma(u[3],  a3, o0);
            o1 = cfma(u[4],  a0, o1); o1 = cfma(u[5],  a1, o1); o1 = cfma(u[6],  a2, o1); o1 = cfma(u[7],  a3, o1);
            o2 = cfma(u[8],  a0, o2); o2 = cfma(u[9],  a1, o2); o2 = cfma(u[10], a2, o2); o2 = cfma(u[11], a3, o2);
            o3 = cfma(u[12], a0, o3); o3 = cfma(u[13], a1, o3); o3 = cfma(u[14], a2, o3); o3 = cfma(u[15], a3, o3);
            st[base] = o0; st[base + s4] = o1; st[base + 2*s4] = o2; st[base + 3*s4] = o3;
        }
        __syncthreads();
    }

    // ---- 3 variational layers: fused RY(4) + local CNOTs, then cross-CNOT permutation ----
    for (int layer = 0; layer < 3; layer++) {
        const float* rc = ry + layer * 28;
        // passes A,B,C: wires 4p..4p+3, bit block lo = 10-4p
        for (int p = 0; p < 3; p++) {
            int lo = 10 - 4 * p, q0 = 4 * p;
            float c0 = rc[2*q0], s0 = rc[2*q0+1];
            float c1 = rc[2*q0+2], s1 = rc[2*q0+3];
            float c2 = rc[2*q0+4], s2 = rc[2*q0+5];
            float c3 = rc[2*q0+6], s3 = rc[2*q0+7];
            for (int grp = tid; grp < 1024; grp += CTHREADS) {
                int low = grp & ((1 << lo) - 1);
                int base = ((grp >> lo) << (lo + 4)) | low;
                float2 v[16];
                #pragma unroll
                for (int k = 0; k < 16; k++) v[k] = st[base + (k << lo)];
                ry16(v, 8, c0, s0); ry16(v, 4, c1, s1);
                ry16(v, 2, c2, s2); ry16(v, 1, c3, s3);
                cnot16(v, 8, 4);   // even CNOT(q0,q0+1)
                cnot16(v, 2, 1);   // even CNOT(q0+2,q0+3)
                cnot16(v, 4, 2);   // odd  CNOT(q0+1,q0+2)
                #pragma unroll
                for (int k = 0; k < 16; k++) st[base + (k << lo)] = v[k];
            }
            __syncthreads();
        }
        // pass D: wires 12,13 (bits 1,0)
        {
            float c12 = rc[24], s12 = rc[25], c13 = rc[26], s13 = rc[27];
            for (int grp = tid; grp < 4096; grp += CTHREADS) {
                int base = grp << 2;
                float2 v[4];
                #pragma unroll
                for (int k = 0; k < 4; k++) v[k] = st[base + k];
                // RY wire12 (bit1): pairs (0,2),(1,3)
                #pragma unroll
                for (int k = 0; k < 2; k++) {
                    float2 a = v[k], bb = v[k | 2];
                    v[k].x = fmaf(c12, a.x, -s12*bb.x); v[k].y = fmaf(c12, a.y, -s12*bb.y);
                    v[k|2].x = fmaf(s12, a.x, c12*bb.x); v[k|2].y = fmaf(s12, a.y, c12*bb.y);
                }
                // RY wire13 (bit0): pairs (0,1),(2,3)
                #pragma unroll
                for (int k = 0; k < 4; k += 2) {
                    float2 a = v[k], bb = v[k | 1];
                    v[k].x = fmaf(c13, a.x, -s13*bb.x); v[k].y = fmaf(c13, a.y, -s13*bb.y);
                    v[k|1].x = fmaf(s13, a.x, c13*bb.x); v[k|1].y = fmaf(s13, a.y, c13*bb.y);
                }
                { float2 t = v[2]; v[2] = v[3]; v[3] = t; }   // CNOT(12,13)
                #pragma unroll
                for (int k = 0; k < 4; k++) st[base + k] = v[k];
            }
            __syncthreads();
        }
        // pass E: cross-boundary odd CNOTs (3,4),(7,8),(11,12) — an involutive permutation
        for (int i = tid; i < DIM; i += CTHREADS) {
            int j = i;
            if (i & (1 << 10)) j ^= (1 << 9);
            if (i & (1 << 6))  j ^= (1 << 5);
            if (i & (1 << 2))  j ^= (1 << 1);
            if (j > i) { float2 t = st[i]; st[i] = st[j]; st[j] = t; }
        }
        __syncthreads();
    }

    // ---- 11 expectation values: Re(v^H H v), triangle form ----
    for (int w = 0; w < NOBS; w++) {
        int lo = 10 - w;
        const float2* Hw = Hsm + w * 256;
        float accD = 0.f, accO = 0.f;
        for (int grp = tid; grp < 1024; grp += CTHREADS) {
            int low = grp & ((1 << lo) - 1);
            int base = ((grp >> lo) << (lo + 4)) | low;
            float2 v[16];
            #pragma unroll
            for (int k = 0; k < 16; k++) v[k] = st[base + (k << lo)];
            #pragma unroll
            for (int k = 0; k < 16; k++) {
                accD = fmaf(Hw[k * 17].x, fmaf(v[k].x, v[k].x, v[k].y * v[k].y), accD);
                #pragma unroll
                for (int l = k + 1; l < 16; l++) {
                    float zr = fmaf(v[k].x, v[l].x,  v[k].y * v[l].y);
                    float zi = fmaf(v[k].x, v[l].y, -v[k].y * v[l].x);
                    float2 h = Hw[k * 16 + l];
                    accO = fmaf(h.x, zr, accO);
                    accO = fmaf(-h.y, zi, accO);
                }
            }
        }
        float acc = accD + 2.f * accO;
        #pragma unroll
        for (int off = 16; off; off >>= 1) acc += __shfl_xor_sync(0xffffffffu, acc, off);
        if ((tid & 31) == 0) red[tid >> 5] = acc;
        __syncthreads();
        if (tid == 0) {
            float t = 0.f;
            #pragma unroll
            for (int i = 0; i < CTHREADS / 32; i++) t += red[i];
            qout[w] = t;
        }
        __syncthreads();
    }

    // ---- head: out[b] = qout @ W_head^T + b_head ----
    if (tid < 10) {
        float o = bh[tid];
        #pragma unroll
        for (int w = 0; w < NOBS; w++) o = fmaf(qout[w], Wh[tid * NOBS + w], o);
        out[b * 10 + tid] = o;
    }
}

// ---------------- launch ----------------
extern "C" void kernel_launch(void* const* d_in, const int* in_sizes, int n_in,
                              void* d_out, int out_size) {
    const float* x    = (const float*)d_in[0];
    const float* W_e  = (const float*)d_in[1];
    const float* b_e  = (const float*)d_in[2];
    const float* var  = (const float*)d_in[3];
    const float* A    = (const float*)d_in[4];
    const float* Bp   = (const float*)d_in[5];
    const float* D    = (const float*)d_in[6];
    const float* Wh   = (const float*)d_in[7];
    const float* bh   = (const float*)d_in[8];
    float* out = (float*)d_out;

    const int SMEM_BYTES = (DIM + 416 + NOBS * 256) * 8 + (84 + 16 + 11) * 4 + 4;
    cudaFuncSetAttribute(circuit_kernel, cudaFuncAttributeMaxDynamicSharedMemorySize, SMEM_BYTES);

    encode_kernel<<<ENC, 128>>>(x, W_e, b_e);
    herm_kernel<<<NOBS, 256>>>(A, Bp, D);
    su4_kernel<<<NGATES, 128>>>();
    circuit_kernel<<<BATCH, CTHREADS, SMEM_BYTES>>>(var, Wh, bh, out);
}

// round 2
// speedup vs baseline: 1.0586x; 1.0586x over previous
#include <cuda_runtime.h>

typedef unsigned long long u64;

#define NQ     14
#define DIM    16384          // 2^14
#define BATCH  128
#define NGATES 26
#define NOBS   11
#define ENC    390
#define INDIM  784
#define CT     512

// ---------------- device scratch ----------------
__device__ float  g_enc[BATCH * ENC];
__device__ float2 g_U[NGATES * BATCH * 16];
__device__ u64    g_Hoff[NOBS * 120];   // packed (re, -im), pair order k<l (k outer)
__device__ u64    g_Hdiag[NOBS * 16];   // packed (h, h)

// ---------------- packed f32x2 helpers ----------------
__device__ __forceinline__ u64 pk2(float lo, float hi) {
    u64 r; asm("mov.b64 %0,{%1,%2};" : "=l"(r) : "f"(lo), "f"(hi)); return r;
}
__device__ __forceinline__ void upk(u64 v, float& lo, float& hi) {
    asm("mov.b64 {%0,%1},%2;" : "=f"(lo), "=f"(hi) : "l"(v));
}
__device__ __forceinline__ u64 f2fma(u64 a, u64 b, u64 c) {
    u64 d; asm("fma.rn.f32x2 %0,%1,%2,%3;" : "=l"(d) : "l"(a), "l"(b), "l"(c)); return d;
}
__device__ __forceinline__ u64 f2mul(u64 a, u64 b) {
    u64 d; asm("mul.rn.f32x2 %0,%1,%2;" : "=l"(d) : "l"(a), "l"(b)); return d;
}
// (re,im) -> (-im, re)   [for u * a complex mult]
__device__ __forceinline__ u64 iswap(u64 v) {
    u64 r; asm("{.reg .f32 lo,hi,nh; mov.b64 {lo,hi},%1; neg.f32 nh,hi; mov.b64 %0,{nh,lo};}"
               : "=l"(r) : "l"(v)); return r;
}
// (re,im) -> (im, -re)   [for conj(v_k) * v_l]
__device__ __forceinline__ u64 jswap(u64 v) {
    u64 r; asm("{.reg .f32 lo,hi,nl; mov.b64 {lo,hi},%1; neg.f32 nl,lo; mov.b64 %0,{hi,nl};}"
               : "=l"(r) : "l"(v)); return r;
}
__device__ __forceinline__ u64 sp_lo(u64 v) {
    u64 r; asm("{.reg .f32 lo,hi; mov.b64 {lo,hi},%1; mov.b64 %0,{lo,lo};}"
               : "=l"(r) : "l"(v)); return r;
}
__device__ __forceinline__ u64 sp_hi(u64 v) {
    u64 r; asm("{.reg .f32 lo,hi; mov.b64 {lo,hi},%1; mov.b64 %0,{hi,hi};}"
               : "=l"(r) : "l"(v)); return r;
}

// ---------------- Pauli table for SU(4) generator ----------------
__constant__ signed char PT[60][4] = {
 {0,1,1,0},{1,0,1,0},{2,3,1,0},{3,2,1,0},          // IX
 {0,1,0,-1},{1,0,0,1},{2,3,0,-1},{3,2,0,1},        // IY
 {0,0,1,0},{1,1,-1,0},{2,2,1,0},{3,3,-1,0},        // IZ
 {0,2,1,0},{1,3,1,0},{2,0,1,0},{3,1,1,0},          // XI
 {0,3,1,0},{1,2,1,0},{2,1,1,0},{3,0,1,0},          // XX
 {0,3,0,-1},{1,2,0,1},{2,1,0,-1},{3,0,0,1},        // XY
 {0,2,1,0},{1,3,-1,0},{2,0,1,0},{3,1,-1,0},        // XZ
 {0,2,0,-1},{1,3,0,-1},{2,0,0,1},{3,1,0,1},        // YI
 {0,3,0,-1},{1,2,0,-1},{2,1,0,1},{3,0,0,1},        // YX
 {0,3,-1,0},{1,2,1,0},{2,1,1,0},{3,0,-1,0},        // YY
 {0,2,0,-1},{1,3,0,1},{2,0,0,1},{3,1,0,-1},        // YZ
 {0,0,1,0},{1,1,1,0},{2,2,-1,0},{3,3,-1,0},        // ZI
 {0,1,1,0},{1,0,1,0},{2,3,-1,0},{3,2,-1,0},        // ZX
 {0,1,0,-1},{1,0,0,1},{2,3,0,1},{3,2,0,-1},        // ZY
 {0,0,1,0},{1,1,-1,0},{2,2,-1,0},{3,3,1,0},        // ZZ
};

// ---------------- kernel 1: encoded = x @ W^T + b (4 j's per block) ----------------
__global__ void encode_kernel(const float* __restrict__ x,
                              const float* __restrict__ W,
                              const float* __restrict__ bv) {
    __shared__ float4 wrow[4][INDIM / 4];           // 12.5 KB
    int j0 = blockIdx.x * 4;
    for (int i = threadIdx.x; i < 4 * (INDIM / 4); i += CT) {
        int jj = i / (INDIM / 4), kk = i % (INDIM / 4);
        int j = j0 + jj; if (j >= ENC) j = ENC - 1;
        wrow[jj][kk] = ((const float4*)(W + (size_t)j * INDIM))[kk];
    }
    __syncthreads();
    int b = threadIdx.x & 127, jj = threadIdx.x >> 7;
    int j = j0 + jj;
    const float4* xr = (const float4*)(x + (size_t)b * INDIM);
    float acc = 0.f;
    #pragma unroll 4
    for (int k = 0; k < INDIM / 4; k++) {
        float4 xa = __ldg(xr + k);
        float4 wa = wrow[jj][k];
        acc = fmaf(xa.x, wa.x, acc); acc = fmaf(xa.y, wa.y, acc);
        acc = fmaf(xa.z, wa.z, acc); acc = fmaf(xa.w, wa.w, acc);
    }
    if (j < ENC) g_enc[b * ENC + j] = acc + bv[j];
}

// ---------------- kernel 2: prepacked Hermitian observables ----------------
__global__ void herm_kernel(const float* __restrict__ A,
                            const float* __restrict__ Bp,
                            const float* __restrict__ D) {
    int w = blockIdx.x;                   // 11 blocks x 128 threads
    int t = threadIdx.x;
    if (t < 120) {
        // pair enumeration: k outer ascending, l = k+1.. ascending
        int k = 0, rem = t;
        while (rem >= 15 - k) { rem -= 15 - k; k++; }
        int l = k + 1 + rem;
        int lp = l * (l - 1) / 2 + k;     // lower-tri storage index for (l,k)
        // H[k][l] = A - iB  ->  packed (re, -im) = (A, +B)
        g_Hoff[w * 120 + t] = pk2(A[w * 120 + lp], Bp[w * 120 + lp]);
    }
    if (t < 16) {
        float dv = (t < 15) ? 2.f * D[w * 16 + t + 1] : 0.f;
        g_Hdiag[w * 16 + t] = pk2(dv, dv);
    }
}

// ---------------- kernel 3: U = expm(i * sum theta_m P_m) ----------------
__device__ __forceinline__ float2 cfma(float2 a, float2 b, float2 c) {
    c.x = fmaf(a.x, b.x, c.x); c.x = fmaf(-a.y, b.y, c.x);
    c.y = fmaf(a.x, b.y, c.y); c.y = fmaf( a.y, b.x, c.y);
    return c;
}
__device__ __forceinline__ void cmm4(const float2* A, const float2* B, float2* C) {
    #pragma unroll
    for (int r = 0; r < 4; r++)
        #pragma unroll
        for (int c = 0; c < 4; c++) {
            float2 acc = make_float2(0.f, 0.f);
            #pragma unroll
            for (int k = 0; k < 4; k++) acc = cfma(A[r*4+k], B[k*4+c], acc);
            C[r*4+c] = acc;
        }
}

__global__ void su4_kernel() {
    int id = blockIdx.x * blockDim.x + threadIdx.x;
    if (id >= NGATES * BATCH) return;
    int g = id >> 7, b = id & 127;
    const float* th = g_enc + b * ENC + g * 15;

    float2 H[16];
    #pragma unroll
    for (int e = 0; e < 16; e++) H[e] = make_float2(0.f, 0.f);
    #pragma unroll
    for (int m = 0; m < 15; m++) {
        float t = th[m];
        #pragma unroll
        for (int e = 0; e < 4; e++) {
            int r = PT[m*4+e][0], c = PT[m*4+e][1];
            H[r*4+c].x = fmaf(t, (float)PT[m*4+e][2], H[r*4+c].x);
            H[r*4+c].y = fmaf(t, (float)PT[m*4+e][3], H[r*4+c].y);
        }
    }
    float fro2 = 0.f;
    #pragma unroll
    for (int e = 0; e < 16; e++) fro2 += H[e].x*H[e].x + H[e].y*H[e].y;
    float fro = sqrtf(fro2);
    int s = 0; float sc = 1.f;
    while (fro * sc > 0.5f && s < 30) { sc *= 0.5f; s++; }

    float2 Am[16];
    #pragma unroll
    for (int e = 0; e < 16; e++) Am[e] = make_float2(-H[e].y * sc, H[e].x * sc);  // i*H*sc

    float2 R[16], Tm[16];
    #pragma unroll
    for (int e = 0; e < 16; e++) R[e] = make_float2((e % 5 == 0) ? 1.f : 0.f, 0.f);
    for (int j = 9; j >= 1; j--) {          // Horner Taylor, |A| <= 0.5
        cmm4(Am, R, Tm);
        float inv = 1.f / (float)j;
        #pragma unroll
        for (int e = 0; e < 16; e++)
            R[e] = make_float2(fmaf(Tm[e].x, inv, (e % 5 == 0) ? 1.f : 0.f), Tm[e].y * inv);
    }
    for (int t2 = 0; t2 < s; t2++) {
        cmm4(R, R, Tm);
        #pragma unroll
        for (int e = 0; e < 16; e++) R[e] = Tm[e];
    }
    #pragma unroll
    for (int e = 0; e < 16; e++) g_U[id * 16 + e] = R[e];
}

// ---------------- packed RY pair op ----------------
__device__ __forceinline__ void rypair(u64& a, u64& b, u64 c2, u64 s2, u64 ns2) {
    u64 na = f2fma(ns2, b, f2mul(c2, a));      // c*a - s*b
    u64 nb = f2fma(c2,  b, f2mul(s2, a));      // s*a + c*b
    a = na; b = nb;
}
__device__ __forceinline__ void ry16p(u64* v, int m, u64 c2, u64 s2, u64 ns2) {
    #pragma unroll
    for (int k = 0; k < 16; k++) if (!(k & m)) rypair(v[k], v[k | m], c2, s2, ns2);
}
__device__ __forceinline__ void cnot16(u64* v, int cm, int tm) {
    #pragma unroll
    for (int k = 0; k < 16; k++)
        if ((k & cm) && !(k & tm)) { u64 t = v[k]; v[k] = v[k | tm]; v[k | tm] = t; }
}

// ---------------- kernel 4: circuit, state in SMEM, packed math ----------------
__global__ void __launch_bounds__(CT, 1)
circuit_kernel(const float* __restrict__ var,
               const float* __restrict__ Wh,
               const float* __restrict__ bh,
               float* __restrict__ out) {
    extern __shared__ u64 sm[];
    u64*   st    = sm;                    // 16384
    u64*   Hoff  = st + DIM;              // 1320
    u64*   Hdiag = Hoff + NOBS * 120;     // 176
    float2* Us   = (float2*)(Hdiag + NOBS * 16);   // 416
    float* ry    = (float*)(Us + NGATES * 16);     // 84
    float* red   = ry + 84;                        // 16
    float* qout  = red + 16;                       // 11

    const int b = blockIdx.x, tid = threadIdx.x;

    for (int i = tid; i < NGATES * 16; i += CT) {
        int g = i >> 4, e = i & 15;
        Us[i] = g_U[((g << 7) | b) * 16 + e];
    }
    for (int i = tid; i < NOBS * 120; i += CT) Hoff[i] = g_Hoff[i];
    for (int i = tid; i < NOBS * 16;  i += CT) Hdiag[i] = g_Hdiag[i];
    for (int i = tid; i < 42; i += CT) {
        float t = var[i] * 0.5f;
        ry[2*i] = cosf(t); ry[2*i+1] = sinf(t);
    }
    for (int i = tid; i < DIM; i += CT)
        st[i] = (i == 0) ? 0x3f800000ULL : 0ULL;
    __syncthreads();

    // ---- 26 SU(4) gates, packed complex ----
    for (int g = 0; g < NGATES; g++) {
        int g13 = g % 13;
        int q = (g13 < 7) ? 2 * g13 : 2 * (g13 - 7) + 1;
        int pos = 12 - q, s4 = 1 << pos;
        u64 uxx[16], uyy[16];
        #pragma unroll
        for (int e = 0; e < 16; e++) {
            float2 ue = Us[g * 16 + e];
            uxx[e] = pk2(ue.x, ue.x);
            uyy[e] = pk2(ue.y, ue.y);
        }
        for (int grp = tid; grp < 4096; grp += CT) {
            int low = grp & (s4 - 1);
            int base = ((grp >> pos) << (pos + 2)) | low;
            u64 a0 = st[base], a1 = st[base + s4], a2 = st[base + 2*s4], a3 = st[base + 3*s4];
            u64 q0 = iswap(a0), q1 = iswap(a1), q2 = iswap(a2), q3 = iswap(a3);
            u64 o0, o1, o2, o3;
            o0 = f2mul(uxx[0],  a0);      o0 = f2fma(uyy[0],  q0, o0);
            o1 = f2mul(uxx[4],  a0);      o1 = f2fma(uyy[4],  q0, o1);
            o2 = f2mul(uxx[8],  a0);      o2 = f2fma(uyy[8],  q0, o2);
            o3 = f2mul(uxx[12], a0);      o3 = f2fma(uyy[12], q0, o3);
            o0 = f2fma(uxx[1],  a1, o0);  o0 = f2fma(uyy[1],  q1, o0);
            o1 = f2fma(uxx[5],  a1, o1);  o1 = f2fma(uyy[5],  q1, o1);
            o2 = f2fma(uxx[9],  a1, o2);  o2 = f2fma(uyy[9],  q1, o2);
            o3 = f2fma(uxx[13], a1, o3);  o3 = f2fma(uyy[13], q1, o3);
            o0 = f2fma(uxx[2],  a2, o0);  o0 = f2fma(uyy[2],  q2, o0);
            o1 = f2fma(uxx[6],  a2, o1);  o1 = f2fma(uyy[6],  q2, o1);
            o2 = f2fma(uxx[10], a2, o2);  o2 = f2fma(uyy[10], q2, o2);
            o3 = f2fma(uxx[14], a2, o3);  o3 = f2fma(uyy[14], q2, o3);
            o0 = f2fma(uxx[3],  a3, o0);  o0 = f2fma(uyy[3],  q3, o0);
            o1 = f2fma(uxx[7],  a3, o1);  o1 = f2fma(uyy[7],  q3, o1);
            o2 = f2fma(uxx[11], a3, o2);  o2 = f2fma(uyy[11], q3, o2);
            o3 = f2fma(uxx[15], a3, o3);  o3 = f2fma(uyy[15], q3, o3);
            st[base] = o0; st[base + s4] = o1; st[base + 2*s4] = o2; st[base + 3*s4] = o3;
        }
        __syncthreads();
    }

    // ---- 3 variational layers ----
    for (int layer = 0; layer < 3; layer++) {
        const float* rc = ry + layer * 28;
        for (int p = 0; p < 3; p++) {
            int lo = 10 - 4 * p, q0 = 4 * p;
            u64 c2[4], s2[4], ns2[4];
            #pragma unroll
            for (int wq = 0; wq < 4; wq++) {
                float c = rc[2*(q0+wq)], s = rc[2*(q0+wq)+1];
                c2[wq] = pk2(c, c); s2[wq] = pk2(s, s); ns2[wq] = pk2(-s, -s);
            }
            for (int grp = tid; grp < 1024; grp += CT) {
                int low = grp & ((1 << lo) - 1);
                int base = ((grp >> lo) << (lo + 4)) | low;
                u64 v[16];
                #pragma unroll
                for (int k = 0; k < 16; k++) v[k] = st[base + (k << lo)];
                ry16p(v, 8, c2[0], s2[0], ns2[0]);
                ry16p(v, 4, c2[1], s2[1], ns2[1]);
                ry16p(v, 2, c2[2], s2[2], ns2[2]);
                ry16p(v, 1, c2[3], s2[3], ns2[3]);
                cnot16(v, 8, 4);
                cnot16(v, 2, 1);
                cnot16(v, 4, 2);
                #pragma unroll
                for (int k = 0; k < 16; k++) st[base + (k << lo)] = v[k];
            }
            __syncthreads();
        }
        // pass D: wires 12,13 (bits 1,0)
        {
            float ca = rc[24], sa = rc[25], cb = rc[26], sb = rc[27];
            u64 c12 = pk2(ca, ca), s12 = pk2(sa, sa), ns12 = pk2(-sa, -sa);
            u64 c13 = pk2(cb, cb), s13 = pk2(sb, sb), ns13 = pk2(-sb, -sb);
            for (int grp = tid; grp < 4096; grp += CT) {
                int base = grp << 2;
                u64 v0 = st[base], v1 = st[base+1], v2 = st[base+2], v3 = st[base+3];
                rypair(v0, v2, c12, s12, ns12);
                rypair(v1, v3, c12, s12, ns12);
                rypair(v0, v1, c13, s13, ns13);
                rypair(v2, v3, c13, s13, ns13);
                { u64 t = v2; v2 = v3; v3 = t; }   // CNOT(12,13)
                st[base] = v0; st[base+1] = v1; st[base+2] = v2; st[base+3] = v3;
            }
            __syncthreads();
        }
        // pass E: cross-boundary odd CNOTs (3,4),(7,8),(11,12)
        for (int i = tid; i < DIM; i += CT) {
            int j = i;
            if (i & (1 << 10)) j ^= (1 << 9);
            if (i & (1 << 6))  j ^= (1 << 5);
            if (i & (1 << 2))  j ^= (1 << 1);
            if (j > i) { u64 t = st[i]; st[i] = st[j]; st[j] = t; }
        }
        __syncthreads();
    }

    // ---- 11 expectation values, packed triangle ----
    for (int w = 0; w < NOBS; w++) {
        int lo = 10 - w;
        const u64* Ho = Hoff + w * 120;
        const u64* Hd = Hdiag + w * 16;
        u64 aD = 0, aO0 = 0, aO1 = 0, aO2 = 0, aO3 = 0;
        for (int grp = tid; grp < 1024; grp += CT) {
            int low = grp & ((1 << lo) - 1);
            int base = ((grp >> lo) << (lo + 4)) | low;
            u64 v[16], qa[16];
            #pragma unroll
            for (int k = 0; k < 16; k++) { v[k] = st[base + (k << lo)]; qa[k] = jswap(v[k]); }
            int p = 0;
            #pragma unroll
            for (int k = 0; k < 16; k++) {
                u64 vx = sp_lo(v[k]), vy = sp_hi(v[k]);
                aD = f2fma(Hd[k], f2mul(v[k], v[k]), aD);
                #pragma unroll
                for (int l = k + 1; l < 16; l++) {
                    u64 z = f2fma(vy, qa[l], f2mul(vx, v[l]));
                    u64 h = Ho[p];
                    switch (p & 3) {
                        case 0: aO0 = f2fma(h, z, aO0); break;
                        case 1: aO1 = f2fma(h, z, aO1); break;
                        case 2: aO2 = f2fma(h, z, aO2); break;
                        default: aO3 = f2fma(h, z, aO3); break;
                    }
                    p++;
                }
            }
        }
        float xr, xi, acc;
        upk(aD, xr, xi); acc = xr + xi;
        float accO = 0.f;
        upk(aO0, xr, xi); accO += xr + xi;
        upk(aO1, xr, xi); accO += xr + xi;
        upk(aO2, xr, xi); accO += xr + xi;
        upk(aO3, xr, xi); accO += xr + xi;
        acc += 2.f * accO;
        #pragma unroll
        for (int off = 16; off; off >>= 1) acc += __shfl_xor_sync(0xffffffffu, acc, off);
        if ((tid & 31) == 0) red[tid >> 5] = acc;
        __syncthreads();
        if (tid == 0) {
            float t = 0.f;
            #pragma unroll
            for (int i = 0; i < CT / 32; i++) t += red[i];
            qout[w] = t;
        }
        __syncthreads();
    }

    // ---- head ----
    if (tid < 10) {
        float o = bh[tid];
        #pragma unroll
        for (int w = 0; w < NOBS; w++) o = fmaf(qout[w], Wh[tid * NOBS + w], o);
        out[b * 10 + tid] = o;
    }
}

// ---------------- launch ----------------
extern "C" void kernel_launch(void* const* d_in, const int* in_sizes, int n_in,
                              void* d_out, int out_size) {
    const float* x    = (const float*)d_in[0];
    const float* W_e  = (const float*)d_in[1];
    const float* b_e  = (const float*)d_in[2];
    const float* var  = (const float*)d_in[3];
    const float* A    = (const float*)d_in[4];
    const float* Bp   = (const float*)d_in[5];
    const float* D    = (const float*)d_in[6];
    const float* Wh   = (const float*)d_in[7];
    const float* bh   = (const float*)d_in[8];
    float* out = (float*)d_out;

    const int SMEM_BYTES = (DIM + NOBS * 120 + NOBS * 16) * 8
                         + NGATES * 16 * 8 + (84 + 16 + 11 + 1) * 4;
    cudaFuncSetAttribute(circuit_kernel, cudaFuncAttributeMaxDynamicSharedMemorySize, SMEM_BYTES);

    encode_kernel<<<(ENC + 3) / 4, CT>>>(x, W_e, b_e);
    herm_kernel<<<NOBS, 128>>>(A, Bp, D);
    su4_kernel<<<NGATES, 128>>>();
    circuit_kernel<<<BATCH, CT, SMEM_BYTES>>>(var, Wh, bh, out);
}